// round 1
// baseline (speedup 1.0000x reference)
#include <cuda_runtime.h>
#include <cstdint>

// ---------------------------------------------------------------------------
// Problem constants
// ---------------------------------------------------------------------------
#define BB   16
#define NN   1024
#define KK   512
#define DIN  64
#define HH   256
#define NHH  8
#define HD   32
#define FF   1024
#define LL   2
#define TOK  (BB * NN)   // 16384 tokens

// ---------------------------------------------------------------------------
// Device scratch (static globals: allocation-free rule)
// ---------------------------------------------------------------------------
__device__ float g_h   [TOK * HH];     // running hidden state
__device__ float g_tmp [TOK * HH];     // pre-LN buffer
__device__ float g_qkv [TOK * 3 * HH]; // qkv projections
__device__ float g_attn[TOK * HH];     // attention output
__device__ float g_ff  [TOK * FF];     // ffn hidden

// ---------------------------------------------------------------------------
// SGEMM: C[M,N] = A[M,K] @ W[K,N] + bias[N] (+ res[M,N]) (+ relu)
// 128x128 block tile, 8x8 per thread, BK=8. fp32 SIMT.
// Requires: M%128==0, N%128==0, K%8==0 (all shapes here satisfy this).
// ---------------------------------------------------------------------------
__global__ __launch_bounds__(256) void sgemm_kernel(
    const float* __restrict__ A, const float* __restrict__ W,
    const float* __restrict__ bias, const float* __restrict__ res,
    float* __restrict__ C, int M, int K, int N, int relu)
{
    __shared__ float As[8][128];
    __shared__ float Bs[8][128];

    const int tid  = threadIdx.x;
    const int m0   = blockIdx.y * 128;
    const int n0   = blockIdx.x * 128;
    const int trow = tid >> 4;        // 0..15 -> rows trow*8..+7
    const int tcol = tid & 15;        // 0..15 -> cols tcol*8..+7

    float acc[8][8];
    #pragma unroll
    for (int i = 0; i < 8; i++)
        #pragma unroll
        for (int j = 0; j < 8; j++) acc[i][j] = 0.f;

    // load assignments
    const int arow = tid >> 1;          // 0..127
    const int acol = (tid & 1) * 4;     // 0 or 4
    const int brow = tid >> 5;          // 0..7
    const int bcol = (tid & 31) * 4;    // 0..124

    const float* Aptr = A + (size_t)(m0 + arow) * K + acol;
    const float* Wptr = W + (size_t)brow * N + (n0 + bcol);

    for (int k0 = 0; k0 < K; k0 += 8) {
        float4 av = *(const float4*)(Aptr + k0);
        As[acol + 0][arow] = av.x;
        As[acol + 1][arow] = av.y;
        As[acol + 2][arow] = av.z;
        As[acol + 3][arow] = av.w;
        *(float4*)&Bs[brow][bcol] = *(const float4*)(Wptr + (size_t)k0 * N);
        __syncthreads();

        #pragma unroll
        for (int k = 0; k < 8; k++) {
            float a[8], b[8];
            *(float4*)&a[0] = *(const float4*)&As[k][trow * 8];
            *(float4*)&a[4] = *(const float4*)&As[k][trow * 8 + 4];
            *(float4*)&b[0] = *(const float4*)&Bs[k][tcol * 8];
            *(float4*)&b[4] = *(const float4*)&Bs[k][tcol * 8 + 4];
            #pragma unroll
            for (int i = 0; i < 8; i++)
                #pragma unroll
                for (int j = 0; j < 8; j++)
                    acc[i][j] += a[i] * b[j];
        }
        __syncthreads();
    }

    // epilogue
    float bv[8];
    #pragma unroll
    for (int j = 0; j < 8; j++) bv[j] = bias[n0 + tcol * 8 + j];

    #pragma unroll
    for (int i = 0; i < 8; i++) {
        const int row = m0 + trow * 8 + i;
        float* Crow = C + (size_t)row * N + n0 + tcol * 8;
        float out[8];
        #pragma unroll
        for (int j = 0; j < 8; j++) out[j] = acc[i][j] + bv[j];
        if (res) {
            const float* Rrow = res + (size_t)row * N + n0 + tcol * 8;
            float4 r0 = *(const float4*)&Rrow[0];
            float4 r1 = *(const float4*)&Rrow[4];
            out[0] += r0.x; out[1] += r0.y; out[2] += r0.z; out[3] += r0.w;
            out[4] += r1.x; out[5] += r1.y; out[6] += r1.z; out[7] += r1.w;
        }
        if (relu) {
            #pragma unroll
            for (int j = 0; j < 8; j++) out[j] = fmaxf(out[j], 0.f);
        }
        *(float4*)&Crow[0] = *(float4*)&out[0];
        *(float4*)&Crow[4] = *(float4*)&out[4];
    }
}

// ---------------------------------------------------------------------------
// Flash-attention (fp32, online softmax). qkv: [TOK, 768], out: [TOK, 256].
// One block per (64 queries, head). K/V streamed in 64-row tiles.
// ---------------------------------------------------------------------------
__global__ __launch_bounds__(256) void attn_kernel(
    const float* __restrict__ qkv, float* __restrict__ out)
{
    const int b  = blockIdx.y >> 3;
    const int h  = blockIdx.y & 7;
    const int q0 = blockIdx.x * 64;
    const int tid = threadIdx.x;

    __shared__ float Qs[64][33];
    __shared__ float Ks[64][33];
    __shared__ float Vs[64][33];
    __shared__ float Ps[64][65];
    __shared__ float m_s[64], l_s[64], sc_s[64];

    const size_t base = (size_t)b * NN;
    const float scale = 0.17677669529663687f;  // 1/sqrt(32)

    // load Q (pre-scaled)
    #pragma unroll
    for (int it = 0; it < 8; it++) {
        int idx = tid + it * 256;
        int r = idx >> 5, d = idx & 31;
        Qs[r][d] = qkv[(base + q0 + r) * 768 + h * 32 + d] * scale;
    }
    if (tid < 64) { m_s[tid] = -1e30f; l_s[tid] = 0.f; }

    // mapping A (score compute): 4x4 tile of 64x64 S
    const int tr = tid >> 4;   // rows tr*4..+3
    const int tc = tid & 15;   // cols tc*4..+3
    // mapping B (O accum): 2 rows x 4 dims of 64x32 O
    const int tidy = tid >> 3; // rows tidy*2, tidy*2+1
    const int tidx = tid & 7;  // dims tidx*4..+3

    float o0[4] = {0.f, 0.f, 0.f, 0.f};
    float o1[4] = {0.f, 0.f, 0.f, 0.f};
    __syncthreads();

    for (int kt = 0; kt < NN / 64; kt++) {
        const int k0 = kt * 64;
        #pragma unroll
        for (int it = 0; it < 8; it++) {
            int idx = tid + it * 256;
            int r = idx >> 5, d = idx & 31;
            size_t t = (base + k0 + r) * 768;
            Ks[r][d] = qkv[t + 256 + h * 32 + d];
            Vs[r][d] = qkv[t + 512 + h * 32 + d];
        }
        __syncthreads();

        // S = Q @ K^T (scaled)
        float s[4][4];
        #pragma unroll
        for (int i = 0; i < 4; i++)
            #pragma unroll
            for (int j = 0; j < 4; j++) s[i][j] = 0.f;

        for (int d = 0; d < 32; d++) {
            float a[4], bb[4];
            #pragma unroll
            for (int i = 0; i < 4; i++) a[i]  = Qs[tr * 4 + i][d];
            #pragma unroll
            for (int j = 0; j < 4; j++) bb[j] = Ks[tc * 4 + j][d];
            #pragma unroll
            for (int i = 0; i < 4; i++)
                #pragma unroll
                for (int j = 0; j < 4; j++)
                    s[i][j] += a[i] * bb[j];
        }

        // online softmax per row (16 threads share a row group of 4 rows)
        #pragma unroll
        for (int i = 0; i < 4; i++) {
            const int row = tr * 4 + i;
            float rmax = fmaxf(fmaxf(s[i][0], s[i][1]), fmaxf(s[i][2], s[i][3]));
            #pragma unroll
            for (int off = 1; off < 16; off <<= 1)
                rmax = fmaxf(rmax, __shfl_xor_sync(0xffffffffu, rmax, off));
            const float m_old = m_s[row];
            const float m_new = fmaxf(m_old, rmax);
            float lsum = 0.f;
            #pragma unroll
            for (int j = 0; j < 4; j++) {
                float p = __expf(s[i][j] - m_new);
                Ps[row][tc * 4 + j] = p;
                lsum += p;
            }
            #pragma unroll
            for (int off = 1; off < 16; off <<= 1)
                lsum += __shfl_xor_sync(0xffffffffu, lsum, off);
            if (tc == 0) {
                const float scl = __expf(m_old - m_new);
                sc_s[row] = scl;
                l_s[row]  = l_s[row] * scl + lsum;
                m_s[row]  = m_new;
            }
        }
        __syncthreads();

        // O = diag(scale)*O + P @ V
        const int r0 = tidy * 2, r1 = r0 + 1;
        const float sc0 = sc_s[r0], sc1 = sc_s[r1];
        #pragma unroll
        for (int dd = 0; dd < 4; dd++) { o0[dd] *= sc0; o1[dd] *= sc1; }
        for (int kk = 0; kk < 64; kk++) {
            const float p0 = Ps[r0][kk];
            const float p1 = Ps[r1][kk];
            #pragma unroll
            for (int dd = 0; dd < 4; dd++) {
                const float v = Vs[kk][tidx * 4 + dd];
                o0[dd] += p0 * v;
                o1[dd] += p1 * v;
            }
        }
        __syncthreads();
    }

    const int r0 = tidy * 2, r1 = r0 + 1;
    const float inv0 = 1.f / l_s[r0];
    const float inv1 = 1.f / l_s[r1];
    #pragma unroll
    for (int dd = 0; dd < 4; dd++) {
        out[(base + q0 + r0) * HH + h * 32 + tidx * 4 + dd] = o0[dd] * inv0;
        out[(base + q0 + r1) * HH + h * 32 + tidx * 4 + dd] = o1[dd] * inv1;
    }
}

// ---------------------------------------------------------------------------
// LayerNorm over last dim (256). Warp per row, 8 rows per block.
// ---------------------------------------------------------------------------
__global__ __launch_bounds__(256) void ln_kernel(
    const float* __restrict__ x, const float* __restrict__ gam,
    const float* __restrict__ bet, float* __restrict__ out)
{
    const int row  = blockIdx.x * 8 + (threadIdx.x >> 5);
    const int lane = threadIdx.x & 31;
    const float* xr = x + (size_t)row * HH;

    float v[8];
    float sum = 0.f;
    #pragma unroll
    for (int i = 0; i < 8; i++) { v[i] = xr[lane + i * 32]; sum += v[i]; }
    #pragma unroll
    for (int off = 16; off; off >>= 1) sum += __shfl_xor_sync(0xffffffffu, sum, off);
    const float mean = sum * (1.f / HH);

    float var = 0.f;
    #pragma unroll
    for (int i = 0; i < 8; i++) { float d = v[i] - mean; var += d * d; }
    #pragma unroll
    for (int off = 16; off; off >>= 1) var += __shfl_xor_sync(0xffffffffu, var, off);
    var *= (1.f / HH);
    const float inv = rsqrtf(var + 1e-5f);

    float* orow = out + (size_t)row * HH;
    #pragma unroll
    for (int i = 0; i < 8; i++) {
        const int c = lane + i * 32;
        orow[c] = (v[i] - mean) * inv * gam[c] + bet[c];
    }
}

// ---------------------------------------------------------------------------
// Output init: indices (as float) + zero the bw region
// ---------------------------------------------------------------------------
__global__ void init_out_kernel(const int* __restrict__ sel, float* __restrict__ out,
                                int out_size, int both)
{
    const int i = blockIdx.x * 256 + threadIdx.x;
    if (i >= out_size) return;
    if (both && i < BB * KK) out[i] = (float)sel[i];
    else out[i] = 0.f;
}

// ---------------------------------------------------------------------------
// Allocation: gather-mean -> ctx = mean@Wc+bc -> scores -> softmax*100 ->
// round -> fix-up -> scatter. One block per batch.
// ---------------------------------------------------------------------------
__global__ __launch_bounds__(256) void alloc_kernel(
    const float* __restrict__ enc, const int* __restrict__ sel,
    const float* __restrict__ Wc, const float* __restrict__ bc,
    float* __restrict__ bw)
{
    __shared__ float mean_s[HH];
    __shared__ float ctx_s[HH];
    __shared__ float sc_s[KK];
    __shared__ float red_s[256];
    __shared__ int   idx_s[KK];

    const int b = blockIdx.x, tid = threadIdx.x;

    idx_s[tid]       = sel[b * KK + tid];
    idx_s[tid + 256] = sel[b * KK + tid + 256];
    __syncthreads();

    // masked mean over gathered rows (thread = channel)
    float acc = 0.f; int cnt = 0;
    for (int k = 0; k < KK; k++) {
        const int idx = idx_s[k];
        if (idx < NN) { acc += enc[((size_t)b * NN + idx) * HH + tid]; cnt++; }
    }
    const float cntf = (float)(cnt > 0 ? cnt : 1);
    mean_s[tid] = acc / cntf;
    __syncthreads();

    // ctx = mean @ Wc + bc
    float c = bc[tid];
    for (int i = 0; i < HH; i++) c += mean_s[i] * Wc[i * HH + tid];
    ctx_s[tid] = c;
    __syncthreads();

    // scores[k] = ctx . enc[idx_k]  (warp per row, strided)
    const int wid = tid >> 5, lane = tid & 31;
    for (int k = wid; k < KK; k += 8) {
        const int idx = idx_s[k];
        float s = -1e30f;
        if (idx < NN) {
            const float* row = enc + ((size_t)b * NN + idx) * HH;
            float part = 0.f;
            #pragma unroll
            for (int i = 0; i < 8; i++) part += ctx_s[lane + i * 32] * row[lane + i * 32];
            #pragma unroll
            for (int off = 16; off; off >>= 1)
                part += __shfl_xor_sync(0xffffffffu, part, off);
            s = part;
        }
        if (lane == 0) sc_s[k] = s;
    }
    __syncthreads();

    // block max
    red_s[tid] = fmaxf(sc_s[tid], sc_s[tid + 256]);
    __syncthreads();
    for (int st = 128; st; st >>= 1) {
        if (tid < st) red_s[tid] = fmaxf(red_s[tid], red_s[tid + st]);
        __syncthreads();
    }
    const float m = red_s[0];
    __syncthreads();

    // exp + sum (invalid -> 0)
    const int i0 = idx_s[tid], i1 = idx_s[tid + 256];
    const float e0 = (i0 < NN) ? expf(sc_s[tid] - m)       : 0.f;
    const float e1 = (i1 < NN) ? expf(sc_s[tid + 256] - m) : 0.f;
    red_s[tid] = e0 + e1;
    __syncthreads();
    for (int st = 128; st; st >>= 1) {
        if (tid < st) red_s[tid] += red_s[tid + st];
        __syncthreads();
    }
    const float denom = red_s[0];
    __syncthreads();

    // rounded allocation (rintf == round-half-even == jnp.round)
    float a0 = rintf(e0 / denom * 100.f);
    float a1 = rintf(e1 / denom * 100.f);
    red_s[tid] = a0 + a1;
    __syncthreads();
    for (int st = 128; st; st >>= 1) {
        if (tid < st) red_s[tid] += red_s[tid + st];
        __syncthreads();
    }
    const float diff = 100.f - red_s[0];
    __syncthreads();

    if (tid == 0 && i0 < NN) a0 += diff;   // thread 0 owns k=0

    if (i0 < NN) bw[b * NN + i0] = a0;
    if (i1 < NN) bw[b * NN + i1] = a1;
}

// ---------------------------------------------------------------------------
// Launch
// ---------------------------------------------------------------------------
extern "C" void kernel_launch(void* const* d_in, const int* in_sizes, int n_in,
                              void* d_out, int out_size)
{
    const float* x     = (const float*)d_in[0];
    const int*   sel   = (const int*)  d_in[1];
    const float* W_in  = (const float*)d_in[2];
    const float* b_in  = (const float*)d_in[3];
    const float* Wqkv  = (const float*)d_in[4];
    const float* bqkv  = (const float*)d_in[5];
    const float* Wo    = (const float*)d_in[6];
    const float* bo    = (const float*)d_in[7];
    const float* ln1g  = (const float*)d_in[8];
    const float* ln1b  = (const float*)d_in[9];
    const float* W1    = (const float*)d_in[10];
    const float* b1    = (const float*)d_in[11];
    const float* W2    = (const float*)d_in[12];
    const float* b2    = (const float*)d_in[13];
    const float* ln2g  = (const float*)d_in[14];
    const float* ln2b  = (const float*)d_in[15];
    const float* Wc    = (const float*)d_in[16];
    const float* bc    = (const float*)d_in[17];

    float *h, *tmp, *qkvb, *attnb, *ffb;
    cudaGetSymbolAddress((void**)&h,     g_h);
    cudaGetSymbolAddress((void**)&tmp,   g_tmp);
    cudaGetSymbolAddress((void**)&qkvb,  g_qkv);
    cudaGetSymbolAddress((void**)&attnb, g_attn);
    cudaGetSymbolAddress((void**)&ffb,   g_ff);

    const dim3 blk(256);

    // h = x @ W_in + b_in
    sgemm_kernel<<<dim3(HH / 128, TOK / 128), blk>>>(
        x, W_in, b_in, nullptr, h, TOK, DIN, HH, 0);

    for (int l = 0; l < LL; l++) {
        // qkv = h @ Wqkv[l] + bqkv[l]
        sgemm_kernel<<<dim3(3 * HH / 128, TOK / 128), blk>>>(
            h, Wqkv + (size_t)l * HH * 3 * HH, bqkv + (size_t)l * 3 * HH,
            nullptr, qkvb, TOK, HH, 3 * HH, 0);

        // attention
        attn_kernel<<<dim3(NN / 64, BB * NHH), blk>>>(qkvb, attnb);

        // tmp = attn @ Wo[l] + bo[l] + h ; h = LN1(tmp)
        sgemm_kernel<<<dim3(HH / 128, TOK / 128), blk>>>(
            attnb, Wo + (size_t)l * HH * HH, bo + (size_t)l * HH,
            h, tmp, TOK, HH, HH, 0);
        ln_kernel<<<TOK / 8, blk>>>(tmp, ln1g + l * HH, ln1b + l * HH, h);

        // ff = relu(h @ W1[l] + b1[l])
        sgemm_kernel<<<dim3(FF / 128, TOK / 128), blk>>>(
            h, W1 + (size_t)l * HH * FF, b1 + (size_t)l * FF,
            nullptr, ffb, TOK, HH, FF, 1);

        // tmp = ff @ W2[l] + b2[l] + h ; h = LN2(tmp)
        sgemm_kernel<<<dim3(HH / 128, TOK / 128), blk>>>(
            ffb, W2 + (size_t)l * FF * HH, b2 + (size_t)l * HH,
            h, tmp, TOK, FF, HH, 0);
        ln_kernel<<<TOK / 8, blk>>>(tmp, ln2g + l * HH, ln2b + l * HH, h);
    }

    // output assembly
    float* outf = (float*)d_out;
    const int idx_elems = BB * KK;          // 8192
    const int bw_elems  = BB * NN;          // 16384
    const int both = (out_size >= idx_elems + bw_elems) ? 1 : 0;
    float* bw = both ? (outf + idx_elems) : outf;

    init_out_kernel<<<(out_size + 255) / 256, blk>>>(sel, outf, out_size, both);
    alloc_kernel<<<BB, blk>>>(h, sel, Wc, bc, bw);
}